// round 4
// baseline (speedup 1.0000x reference)
#include <cuda_runtime.h>
#include <cstdint>

#define FULLMASK 0xffffffffu

// Problem constants (fixed dataset)
constexpr int NNODES = 100000;
constexpr int NEDGES = 1000000;
constexpr int HDIM   = 64;
constexpr int ODIM   = 16;
constexpr int RNUM   = 90;
constexpr int BNUM   = 8;

constexpr int TE     = 512;   // edges per tile (one relation per tile)
constexpr int EWARPS = 4;     // warps per edge-block
constexpr int EBATCH = 8;     // edges per warp per pass
constexpr int MAX_TILES = NEDGES / TE + RNUM + 8;

// ---------------- scratch (device globals; no allocation) ----------------
__device__ float g_h0[(size_t)NNODES * HDIM];
__device__ float g_h1[(size_t)NNODES * HDIM];
__device__ float g_Wp[RNUM * HDIM * HDIM];   // packed per-relation weights (reused per layer)
__device__ int   g_hist[RNUM];
__device__ int   g_cursor[RNUM];
__device__ int4  g_tiles[MAX_TILES];         // {rel, start, len, 0}
__device__ int   g_numTiles;
__device__ int   g_ssrc[NEDGES];
__device__ int   g_sdst[NEDGES];
__device__ float g_snorm[NEDGES];

// ---------------- f32x2 helpers ----------------
__device__ __forceinline__ unsigned long long pack2(float lo, float hi) {
    unsigned long long r;
    asm("mov.b64 %0, {%1, %2};" : "=l"(r) : "f"(lo), "f"(hi));
    return r;
}
__device__ __forceinline__ float2 unpack2(unsigned long long v) {
    float2 f;
    asm("mov.b64 {%0, %1}, %2;" : "=f"(f.x), "=f"(f.y) : "l"(v));
    return f;
}
__device__ __forceinline__ unsigned long long fma2(unsigned long long a,
                                                   unsigned long long b,
                                                   unsigned long long c) {
    unsigned long long d;
    asm("fma.rn.f32x2 %0, %1, %2, %3;" : "=l"(d) : "l"(a), "l"(b), "l"(c));
    return d;
}

// ---------------- sort-by-relation (counting sort, reused by all 3 layers) ----------------
__global__ void k_zero() {
    if (threadIdx.x < RNUM) g_hist[threadIdx.x] = 0;
}

__global__ void k_hist(const int* __restrict__ et, int E) {
    __shared__ int h[RNUM];
    for (int i = threadIdx.x; i < RNUM; i += blockDim.x) h[i] = 0;
    __syncthreads();
    for (int e = blockIdx.x * blockDim.x + threadIdx.x; e < E; e += gridDim.x * blockDim.x)
        atomicAdd(&h[et[e]], 1);
    __syncthreads();
    for (int i = threadIdx.x; i < RNUM; i += blockDim.x)
        if (h[i]) atomicAdd(&g_hist[i], h[i]);
}

__global__ void k_scan() {
    if (threadIdx.x == 0 && blockIdx.x == 0) {
        int running = 0, n = 0;
        for (int r = 0; r < RNUM; r++) {
            int c = g_hist[r];
            g_cursor[r] = running;
            int t = 0;
            while (t < c) {
                int len = (c - t < TE) ? (c - t) : TE;
                g_tiles[n] = make_int4(r, running + t, len, 0);
                n++;
                t += TE;
            }
            running += c;
        }
        g_numTiles = n;
    }
}

__global__ void k_scatter(const int* __restrict__ src, const int* __restrict__ dst,
                          const int* __restrict__ et, const float* __restrict__ norm, int E) {
    for (int e = blockIdx.x * blockDim.x + threadIdx.x; e < E; e += gridDim.x * blockDim.x) {
        int t = et[e];
        int p = atomicAdd(&g_cursor[t], 1);
        g_ssrc[p]  = src[e];
        g_sdst[p]  = dst[e];
        g_snorm[p] = norm[e];
    }
}

// ---------------- weight packing ----------------
// Layer 64->64: float layout idx = r*4096 + k*128 + j*8 + rr*4 + cc
// entry(16B) [(k*16+j)*2+rr] = { W[2k+rr][4j], W[2k+rr][4j+1], W[2k+rr][4j+2], W[2k+rr][4j+3] }
__global__ void k_packW64(const float* __restrict__ coeff, const float* __restrict__ bases) {
    int idx = blockIdx.x * blockDim.x + threadIdx.x;
    if (idx >= RNUM * 4096) return;
    int r   = idx >> 12;
    int rem = idx & 4095;
    int k   = rem >> 7;
    int j   = (rem >> 3) & 15;
    int rr  = (rem >> 2) & 1;
    int cc  = rem & 3;
    int row = 2 * k + rr, col = 4 * j + cc;
    float v = 0.f;
#pragma unroll
    for (int b = 0; b < BNUM; b++)
        v += coeff[r * BNUM + b] * bases[(b * HDIM + row) * HDIM + col];
    g_Wp[idx] = v;
}

// Layer 64->16: float layout idx = r*1024 + rp*32 + j*2 + rr
// entry(8B) [rp*16+j] = { W[2rp][j], W[2rp+1][j] }
__global__ void k_packW16(const float* __restrict__ coeff, const float* __restrict__ bases) {
    int idx = blockIdx.x * blockDim.x + threadIdx.x;
    if (idx >= RNUM * 1024) return;
    int r   = idx >> 10;
    int rem = idx & 1023;
    int rp  = rem >> 5;
    int j   = (rem >> 1) & 15;
    int rr  = rem & 1;
    int row = 2 * rp + rr;
    float v = 0.f;
#pragma unroll
    for (int b = 0; b < BNUM; b++)
        v += coeff[r * BNUM + b] * bases[(b * HDIM + row) * ODIM + j];
    g_Wp[idx] = v;
}

__global__ void k_init(float* __restrict__ h, const float* __restrict__ bias,
                       int total, int mask) {
    int i = blockIdx.x * blockDim.x + threadIdx.x;
    if (i < total) h[i] = bias[i & mask];
}

// ---------------- edge kernel, 64 output cols ----------------
// Block: 4 warps, one tile (<=512 edges, single relation). W_r staged in smem.
// Warp pass: 8 edges; lane = half*16 + j ; half-warp h handles edges 4h..4h+3,
// lane owns output cols 4j..4j+3 (two f32x2 accumulators per edge).
template <bool RELU>
__global__ void __launch_bounds__(EWARPS * 32)
k_edge64(const float* __restrict__ x, float* __restrict__ hout) {
    __shared__ ulonglong2 sW[32 * 32];                   // 16 KB
    __shared__ ulonglong2 sX[EWARPS][EBATCH][32];        // 16 KB (splatted, norm-prescaled x)

    int tb = blockIdx.x;
    if (tb >= g_numTiles) return;
    int4 tile = g_tiles[tb];
    int rel = tile.x, start = tile.y, len = tile.z;

    {   // stage W_r (16 KB) into smem
        const float4* wg = (const float4*)(g_Wp + (size_t)rel * 4096);
        float4* ws = (float4*)sW;
        for (int i = threadIdx.x; i < 1024; i += blockDim.x) ws[i] = wg[i];
    }
    __syncthreads();

    const int warp = threadIdx.x >> 5;
    const int lane = threadIdx.x & 31;
    const int half = lane >> 4;
    const int j    = lane & 15;
    const float2* x2 = (const float2*)x;

    for (int base = warp * EBATCH; base < len; base += EWARPS * EBATCH) {
        __syncwarp();
        // edge metadata: lanes 0..7 own edges base..base+7
        int s = 0, d = 0;
        float nm = 0.f;
        if (lane < EBATCH && base + lane < len) {
            int p = start + base + lane;
            s  = g_ssrc[p];
            d  = g_sdst[p];
            nm = g_snorm[p];
        }
        // stage x rows: splatted pairs, pre-scaled by norm (and relu'd)
#pragma unroll
        for (int e = 0; e < EBATCH; e++) {
            int   ss = __shfl_sync(FULLMASK, s, e);
            float nn = __shfl_sync(FULLMASK, nm, e);
            float2 v = x2[(size_t)ss * 32 + lane];
            if (RELU) { v.x = fmaxf(v.x, 0.f); v.y = fmaxf(v.y, 0.f); }
            v.x *= nn; v.y *= nn;
            sX[warp][e][lane] = make_ulonglong2(pack2(v.x, v.x), pack2(v.y, v.y));
        }
        __syncwarp();

        unsigned long long a0[4], a1[4];
#pragma unroll
        for (int e = 0; e < 4; e++) { a0[e] = 0ull; a1[e] = 0ull; }

#pragma unroll
        for (int k = 0; k < 32; k++) {
            ulonglong2 w0 = sW[(k * 16 + j) * 2 + 0];  // row 2k,   cols 4j..4j+3
            ulonglong2 w1 = sW[(k * 16 + j) * 2 + 1];  // row 2k+1, cols 4j..4j+3
#pragma unroll
            for (int e = 0; e < 4; e++) {
                ulonglong2 xp = sX[warp][half * 4 + e][k];  // {splat x[2k], splat x[2k+1]}
                a0[e] = fma2(xp.x, w0.x, a0[e]);
                a1[e] = fma2(xp.x, w0.y, a1[e]);
                a0[e] = fma2(xp.y, w1.x, a0[e]);
                a1[e] = fma2(xp.y, w1.y, a1[e]);
            }
        }

#pragma unroll
        for (int e = 0; e < 4; e++) {
            int de = __shfl_sync(FULLMASK, d, half * 4 + e);
            float2 lo = unpack2(a0[e]);
            float2 hi = unpack2(a1[e]);
            atomicAdd((float4*)(hout + (size_t)de * 64 + j * 4),
                      make_float4(lo.x, lo.y, hi.x, hi.y));
        }
    }
}

// ---------------- edge kernel, 16 output cols (final layer) ----------------
// lane = half*16 + j : half splits the i-range (i in [32h, 32h+32)), lane owns col j.
__global__ void __launch_bounds__(EWARPS * 32)
k_edge16(const float* __restrict__ x, float* __restrict__ out) {
    __shared__ unsigned long long sW2[32 * 16];          // 4 KB
    __shared__ unsigned long long sX2[EWARPS][EBATCH][32]; // 8 KB (plain pairs)

    int tb = blockIdx.x;
    if (tb >= g_numTiles) return;
    int4 tile = g_tiles[tb];
    int rel = tile.x, start = tile.y, len = tile.z;

    {
        const unsigned long long* wg = (const unsigned long long*)(g_Wp + (size_t)rel * 1024);
        for (int i = threadIdx.x; i < 512; i += blockDim.x) sW2[i] = wg[i];
    }
    __syncthreads();

    const int warp = threadIdx.x >> 5;
    const int lane = threadIdx.x & 31;
    const int half = lane >> 4;
    const int j    = lane & 15;
    const float2* x2 = (const float2*)x;

    // hoist this lane's W column pairs into registers (shared across all edges)
    unsigned long long wr[16];
#pragma unroll
    for (int t = 0; t < 16; t++) wr[t] = sW2[(half * 16 + t) * 16 + j];

    for (int base = warp * EBATCH; base < len; base += EWARPS * EBATCH) {
        __syncwarp();
        int s = 0, d = 0;
        float nm = 0.f;
        if (lane < EBATCH && base + lane < len) {
            int p = start + base + lane;
            s  = g_ssrc[p];
            d  = g_sdst[p];
            nm = g_snorm[p];
        }
#pragma unroll
        for (int e = 0; e < EBATCH; e++) {
            int   ss = __shfl_sync(FULLMASK, s, e);
            float nn = __shfl_sync(FULLMASK, nm, e);
            float2 v = x2[(size_t)ss * 32 + lane];
            v.x = fmaxf(v.x, 0.f); v.y = fmaxf(v.y, 0.f);   // final layer always relu's input
            v.x *= nn; v.y *= nn;
            sX2[warp][e][lane] = pack2(v.x, v.y);
        }
        __syncwarp();

#pragma unroll
        for (int e = 0; e < EBATCH; e++) {
            unsigned long long acc = 0ull;
#pragma unroll
            for (int t = 0; t < 16; t++)
                acc = fma2(sX2[warp][e][half * 16 + t], wr[t], acc);
            float2 pr = unpack2(acc);
            float  rs = pr.x + pr.y;
            rs += __shfl_xor_sync(FULLMASK, rs, 16);      // combine the two i-halves
            float v1 = __shfl_down_sync(FULLMASK, rs, 1);
            float v2 = __shfl_down_sync(FULLMASK, rs, 2);
            float v3 = __shfl_down_sync(FULLMASK, rs, 3);
            int de = __shfl_sync(FULLMASK, d, e);
            if (half == 0 && (j & 3) == 0)
                atomicAdd((float4*)(out + (size_t)de * 16 + j),
                          make_float4(rs, v1, v2, v3));
        }
    }
}

// ---------------- launch ----------------
extern "C" void kernel_launch(void* const* d_in, const int* in_sizes, int n_in,
                              void* d_out, int out_size) {
    const float* feats  = (const float*)d_in[0];
    const float* coeff0 = (const float*)d_in[1];
    const float* bases0 = (const float*)d_in[2];
    const float* bias0  = (const float*)d_in[3];
    const float* coeff1 = (const float*)d_in[4];
    const float* bases1 = (const float*)d_in[5];
    const float* bias1  = (const float*)d_in[6];
    const float* coeff2 = (const float*)d_in[7];
    const float* bases2 = (const float*)d_in[8];
    const float* bias2  = (const float*)d_in[9];
    const int*   src    = (const int*)d_in[10];
    const int*   dst    = (const int*)d_in[11];
    const int*   etype  = (const int*)d_in[12];
    const float* norm   = (const float*)d_in[13];
    float* out = (float*)d_out;

    int E = in_sizes[10];
    if (E > NEDGES) E = NEDGES;
    int N = in_sizes[0] / HDIM;
    if (N > NNODES) N = NNODES;

    float* h0;  cudaGetSymbolAddress((void**)&h0, g_h0);
    float* h1;  cudaGetSymbolAddress((void**)&h1, g_h1);

    // ---- sort edges by relation (shared by all 3 layers) ----
    k_zero<<<1, 128>>>();
    k_hist<<<512, 256>>>(etype, E);
    k_scan<<<1, 32>>>();
    k_scatter<<<512, 256>>>(src, dst, etype, norm, E);

    int gridTiles = MAX_TILES;

    // ---- layer 0: feats -> h0 (relu applied by next layer's reader) ----
    k_packW64<<<(RNUM * 4096 + 255) / 256, 256>>>(coeff0, bases0);
    k_init<<<(N * HDIM + 255) / 256, 256>>>(h0, bias0, N * HDIM, HDIM - 1);
    k_edge64<false><<<gridTiles, EWARPS * 32>>>(feats, h0);

    // ---- layer 1: relu(h0) -> h1 ----
    k_packW64<<<(RNUM * 4096 + 255) / 256, 256>>>(coeff1, bases1);
    k_init<<<(N * HDIM + 255) / 256, 256>>>(h1, bias1, N * HDIM, HDIM - 1);
    k_edge64<true><<<gridTiles, EWARPS * 32>>>(h0, h1);

    // ---- layer 2: relu(h1) -> out ----
    k_packW16<<<(RNUM * 1024 + 255) / 256, 256>>>(coeff2, bases2);
    k_init<<<(N * ODIM + 255) / 256, 256>>>(out, bias2, N * ODIM, ODIM - 1);
    k_edge16<<<gridTiles, EWARPS * 32>>>(h1, out);
}

// round 5
// speedup vs baseline: 1.3303x; 1.3303x over previous
#include <cuda_runtime.h>
#include <cstdint>

#define FULLMASK 0xffffffffu

// Problem constants (fixed dataset)
constexpr int NNODES = 100000;
constexpr int NEDGES = 1000000;
constexpr int HDIM   = 64;
constexpr int ODIM   = 16;
constexpr int RNUM   = 90;
constexpr int BNUM   = 8;

constexpr int TE      = 512;   // edges per tile (one relation per tile)
constexpr int EWARPS  = 4;     // warps per edge-block
constexpr int EBATCH  = 8;     // edges per warp per pass
constexpr int SBLOCKS = 512;   // blocks for hist/scatter
constexpr int MAX_TILES = NEDGES / TE + RNUM + 8;

// ---------------- scratch (device globals; no allocation) ----------------
__device__ float g_h0[(size_t)NNODES * HDIM];
__device__ float g_h1[(size_t)NNODES * HDIM];
__device__ float g_Wp[RNUM * HDIM * HDIM];   // packed per-relation weights (reused per layer)
__device__ int   g_hist[RNUM];
__device__ int   g_bh[SBLOCKS * RNUM];       // per-block relation histograms
__device__ int   g_bo[SBLOCKS * RNUM];       // per-block scatter offsets
__device__ int4  g_tiles[MAX_TILES];         // {rel, start, len, 0}
__device__ int   g_numTiles;
__device__ int4  g_edges[NEDGES];            // {src, dst, bits(norm), 0} sorted by relation

// ---------------- f32x2 helpers ----------------
__device__ __forceinline__ unsigned long long pack2(float lo, float hi) {
    unsigned long long r;
    asm("mov.b64 %0, {%1, %2};" : "=l"(r) : "f"(lo), "f"(hi));
    return r;
}
__device__ __forceinline__ float2 unpack2(unsigned long long v) {
    float2 f;
    asm("mov.b64 {%0, %1}, %2;" : "=f"(f.x), "=f"(f.y) : "l"(v));
    return f;
}
__device__ __forceinline__ unsigned long long fma2(unsigned long long a,
                                                   unsigned long long b,
                                                   unsigned long long c) {
    unsigned long long d;
    asm("fma.rn.f32x2 %0, %1, %2, %3;" : "=l"(d) : "l"(a), "l"(b), "l"(c));
    return d;
}

// ---------------- hierarchical counting sort by relation ----------------
__global__ void k_hist(const int* __restrict__ et, int E) {
    __shared__ int h[RNUM];
    for (int i = threadIdx.x; i < RNUM; i += blockDim.x) h[i] = 0;
    __syncthreads();
    int chunk = (E + SBLOCKS - 1) / SBLOCKS;
    int lo = blockIdx.x * chunk;
    int hi = min(E, lo + chunk);
    for (int e = lo + threadIdx.x; e < hi; e += blockDim.x)
        atomicAdd(&h[et[e]], 1);
    __syncthreads();
    for (int i = threadIdx.x; i < RNUM; i += blockDim.x)
        g_bh[blockIdx.x * RNUM + i] = h[i];
}

// Single block: per-relation scan over block hists, tile list, global offsets.
__global__ void k_offsets() {
    __shared__ int relStart[RNUM];
    int r = threadIdx.x;
    if (r < RNUM) {
        int running = 0;
        for (int blk = 0; blk < SBLOCKS; blk++) {
            g_bo[blk * RNUM + r] = running;
            running += g_bh[blk * RNUM + r];
        }
        g_hist[r] = running;   // per-relation count
    }
    __syncthreads();
    if (threadIdx.x == 0) {
        int running = 0, n = 0;
        for (int rr = 0; rr < RNUM; rr++) {
            relStart[rr] = running;
            int c = g_hist[rr];
            int t = 0;
            while (t < c) {
                int len = (c - t < TE) ? (c - t) : TE;
                g_tiles[n] = make_int4(rr, running + t, len, 0);
                n++;
                t += TE;
            }
            running += c;
        }
        g_numTiles = n;
    }
    __syncthreads();
    if (r < RNUM) {
        int rs = relStart[r];
        for (int blk = 0; blk < SBLOCKS; blk++)
            g_bo[blk * RNUM + r] += rs;
    }
}

__global__ void k_scatter(const int* __restrict__ src, const int* __restrict__ dst,
                          const int* __restrict__ et, const float* __restrict__ norm, int E) {
    __shared__ int cur[RNUM];
    for (int i = threadIdx.x; i < RNUM; i += blockDim.x)
        cur[i] = g_bo[blockIdx.x * RNUM + i];
    __syncthreads();
    int chunk = (E + SBLOCKS - 1) / SBLOCKS;
    int lo = blockIdx.x * chunk;
    int hi = min(E, lo + chunk);
    for (int e = lo + threadIdx.x; e < hi; e += blockDim.x) {
        int r = et[e];
        int p = atomicAdd(&cur[r], 1);
        g_edges[p] = make_int4(src[e], dst[e], __float_as_int(norm[e]), 0);
    }
}

// ---------------- weight packing ----------------
// Layer 64->64: plain row-major W_r (conflict-free LDS.128 with j innermost:
// 16B entry [row*16 + j] = { W[row][4j .. 4j+3] })
__global__ void k_packW64(const float* __restrict__ coeff, const float* __restrict__ bases) {
    int idx = blockIdx.x * blockDim.x + threadIdx.x;
    if (idx >= RNUM * 4096) return;
    int r   = idx >> 12;
    int row = (idx >> 6) & 63;
    int col = idx & 63;
    float v = 0.f;
#pragma unroll
    for (int b = 0; b < BNUM; b++)
        v += coeff[r * BNUM + b] * bases[(b * HDIM + row) * HDIM + col];
    g_Wp[idx] = v;
}

// Layer 64->16: float layout idx = r*1024 + rp*32 + j*2 + rr
// entry(8B) [rp*16+j] = { W[2rp][j], W[2rp+1][j] }
__global__ void k_packW16(const float* __restrict__ coeff, const float* __restrict__ bases) {
    int idx = blockIdx.x * blockDim.x + threadIdx.x;
    if (idx >= RNUM * 1024) return;
    int r   = idx >> 10;
    int rem = idx & 1023;
    int rp  = rem >> 5;
    int j   = (rem >> 1) & 15;
    int rr  = rem & 1;
    int row = 2 * rp + rr;
    float v = 0.f;
#pragma unroll
    for (int b = 0; b < BNUM; b++)
        v += coeff[r * BNUM + b] * bases[(b * HDIM + row) * ODIM + j];
    g_Wp[idx] = v;
}

__global__ void k_init(float* __restrict__ h, const float* __restrict__ bias,
                       int total, int mask) {
    int i = blockIdx.x * blockDim.x + threadIdx.x;
    if (i < total) h[i] = bias[i & mask];
}

// ---------------- edge kernel, 64 output cols ----------------
// Block: 4 warps, one tile (<=512 edges, single relation). W_r staged in smem.
// Warp pass: 8 edges; lane = half*16 + j ; half-warp h handles edges 4h..4h+3,
// lane owns output cols 4j..4j+3 (two f32x2 accumulators per edge).
template <bool RELU>
__global__ void __launch_bounds__(EWARPS * 32)
k_edge64(const float* __restrict__ x, float* __restrict__ hout) {
    __shared__ ulonglong2 sW[64 * 16];                   // 16 KB, row-major, j innermost
    __shared__ ulonglong2 sX[EWARPS][EBATCH][32];        // 16 KB (splatted, norm-prescaled x)

    int tb = blockIdx.x;
    if (tb >= g_numTiles) return;
    int4 tile = g_tiles[tb];
    int rel = tile.x, start = tile.y, len = tile.z;

    {   // stage W_r (16 KB) into smem
        const float4* wg = (const float4*)(g_Wp + (size_t)rel * 4096);
        float4* ws = (float4*)sW;
        for (int i = threadIdx.x; i < 1024; i += blockDim.x) ws[i] = wg[i];
    }
    __syncthreads();

    const int warp = threadIdx.x >> 5;
    const int lane = threadIdx.x & 31;
    const int half = lane >> 4;
    const int j    = lane & 15;
    const float2* x2 = (const float2*)x;

    for (int base = warp * EBATCH; base < len; base += EWARPS * EBATCH) {
        __syncwarp();
        // edge metadata: lanes 0..7 own edges base..base+7 (one LDG.128)
        int4 ed = make_int4(0, 0, 0, 0);
        if (lane < EBATCH && base + lane < len)
            ed = g_edges[start + base + lane];
        int s = ed.x, d = ed.y;
        float nm = __int_as_float(ed.z);

        // stage x rows: splatted pairs, pre-scaled by norm (and relu'd)
#pragma unroll
        for (int e = 0; e < EBATCH; e++) {
            int   ss = __shfl_sync(FULLMASK, s, e);
            float nn = __shfl_sync(FULLMASK, nm, e);
            float2 v = x2[(size_t)ss * 32 + lane];
            if (RELU) { v.x = fmaxf(v.x, 0.f); v.y = fmaxf(v.y, 0.f); }
            v.x *= nn; v.y *= nn;
            sX[warp][e][lane] = make_ulonglong2(pack2(v.x, v.x), pack2(v.y, v.y));
        }
        __syncwarp();

        unsigned long long a0[4], a1[4];
#pragma unroll
        for (int e = 0; e < 4; e++) { a0[e] = 0ull; a1[e] = 0ull; }

#pragma unroll
        for (int k = 0; k < 32; k++) {
            ulonglong2 w0 = sW[(2 * k)     * 16 + j];  // row 2k,   cols 4j..4j+3
            ulonglong2 w1 = sW[(2 * k + 1) * 16 + j];  // row 2k+1, cols 4j..4j+3
#pragma unroll
            for (int e = 0; e < 4; e++) {
                ulonglong2 xp = sX[warp][half * 4 + e][k];  // {splat x[2k], splat x[2k+1]}
                a0[e] = fma2(xp.x, w0.x, a0[e]);
                a1[e] = fma2(xp.x, w0.y, a1[e]);
                a0[e] = fma2(xp.y, w1.x, a0[e]);
                a1[e] = fma2(xp.y, w1.y, a1[e]);
            }
        }

#pragma unroll
        for (int e = 0; e < 4; e++) {
            int de = __shfl_sync(FULLMASK, d, half * 4 + e);
            float2 lo = unpack2(a0[e]);
            float2 hi = unpack2(a1[e]);
            atomicAdd((float4*)(hout + (size_t)de * 64 + j * 4),
                      make_float4(lo.x, lo.y, hi.x, hi.y));
        }
    }
}

// ---------------- edge kernel, 16 output cols (final layer) ----------------
// lane = half*16 + j : half splits the i-range (i in [32h, 32h+32)), lane owns col j.
__global__ void __launch_bounds__(EWARPS * 32)
k_edge16(const float* __restrict__ x, float* __restrict__ out) {
    __shared__ unsigned long long sW2[32 * 16];            // 4 KB
    __shared__ unsigned long long sX2[EWARPS][EBATCH][32]; // 8 KB (plain pairs)

    int tb = blockIdx.x;
    if (tb >= g_numTiles) return;
    int4 tile = g_tiles[tb];
    int rel = tile.x, start = tile.y, len = tile.z;

    {
        const unsigned long long* wg = (const unsigned long long*)(g_Wp + (size_t)rel * 1024);
        for (int i = threadIdx.x; i < 512; i += blockDim.x) sW2[i] = wg[i];
    }
    __syncthreads();

    const int warp = threadIdx.x >> 5;
    const int lane = threadIdx.x & 31;
    const int half = lane >> 4;
    const int j    = lane & 15;
    const float2* x2 = (const float2*)x;

    // hoist this lane's W column pairs into registers (shared across all edges)
    unsigned long long wr[16];
#pragma unroll
    for (int t = 0; t < 16; t++) wr[t] = sW2[(half * 16 + t) * 16 + j];

    for (int base = warp * EBATCH; base < len; base += EWARPS * EBATCH) {
        __syncwarp();
        int4 ed = make_int4(0, 0, 0, 0);
        if (lane < EBATCH && base + lane < len)
            ed = g_edges[start + base + lane];
        int s = ed.x, d = ed.y;
        float nm = __int_as_float(ed.z);

#pragma unroll
        for (int e = 0; e < EBATCH; e++) {
            int   ss = __shfl_sync(FULLMASK, s, e);
            float nn = __shfl_sync(FULLMASK, nm, e);
            float2 v = x2[(size_t)ss * 32 + lane];
            v.x = fmaxf(v.x, 0.f); v.y = fmaxf(v.y, 0.f);   // final layer always relu's input
            v.x *= nn; v.y *= nn;
            sX2[warp][e][lane] = pack2(v.x, v.y);
        }
        __syncwarp();

#pragma unroll
        for (int e = 0; e < EBATCH; e++) {
            unsigned long long acc = 0ull;
#pragma unroll
            for (int t = 0; t < 16; t++)
                acc = fma2(sX2[warp][e][half * 16 + t], wr[t], acc);
            float2 pr = unpack2(acc);
            float  rs = pr.x + pr.y;
            rs += __shfl_xor_sync(FULLMASK, rs, 16);      // combine the two i-halves
            float v1 = __shfl_down_sync(FULLMASK, rs, 1);
            float v2 = __shfl_down_sync(FULLMASK, rs, 2);
            float v3 = __shfl_down_sync(FULLMASK, rs, 3);
            int de = __shfl_sync(FULLMASK, d, e);
            if (half == 0 && (j & 3) == 0)
                atomicAdd((float4*)(out + (size_t)de * 16 + j),
                          make_float4(rs, v1, v2, v3));
        }
    }
}

// ---------------- launch ----------------
extern "C" void kernel_launch(void* const* d_in, const int* in_sizes, int n_in,
                              void* d_out, int out_size) {
    const float* feats  = (const float*)d_in[0];
    const float* coeff0 = (const float*)d_in[1];
    const float* bases0 = (const float*)d_in[2];
    const float* bias0  = (const float*)d_in[3];
    const float* coeff1 = (const float*)d_in[4];
    const float* bases1 = (const float*)d_in[5];
    const float* bias1  = (const float*)d_in[6];
    const float* coeff2 = (const float*)d_in[7];
    const float* bases2 = (const float*)d_in[8];
    const float* bias2  = (const float*)d_in[9];
    const int*   src    = (const int*)d_in[10];
    const int*   dst    = (const int*)d_in[11];
    const int*   etype  = (const int*)d_in[12];
    const float* norm   = (const float*)d_in[13];
    float* out = (float*)d_out;

    int E = in_sizes[10];
    if (E > NEDGES) E = NEDGES;
    int N = in_sizes[0] / HDIM;
    if (N > NNODES) N = NNODES;

    float* h0;  cudaGetSymbolAddress((void**)&h0, g_h0);
    float* h1;  cudaGetSymbolAddress((void**)&h1, g_h1);

    // ---- sort edges by relation (shared by all 3 layers) ----
    k_hist<<<SBLOCKS, 256>>>(etype, E);
    k_offsets<<<1, 128>>>();
    k_scatter<<<SBLOCKS, 256>>>(src, dst, etype, norm, E);

    int gridTiles = MAX_TILES;

    // ---- layer 0: feats -> h0 (relu applied by next layer's reader) ----
    k_packW64<<<(RNUM * 4096 + 255) / 256, 256>>>(coeff0, bases0);
    k_init<<<(N * HDIM + 255) / 256, 256>>>(h0, bias0, N * HDIM, HDIM - 1);
    k_edge64<false><<<gridTiles, EWARPS * 32>>>(feats, h0);

    // ---- layer 1: relu(h0) -> h1 ----
    k_packW64<<<(RNUM * 4096 + 255) / 256, 256>>>(coeff1, bases1);
    k_init<<<(N * HDIM + 255) / 256, 256>>>(h1, bias1, N * HDIM, HDIM - 1);
    k_edge64<true><<<gridTiles, EWARPS * 32>>>(h0, h1);

    // ---- layer 2: relu(h1) -> out ----
    k_packW16<<<(RNUM * 1024 + 255) / 256, 256>>>(coeff2, bases2);
    k_init<<<(N * ODIM + 255) / 256, 256>>>(out, bias2, N * ODIM, ODIM - 1);
    k_edge16<<<gridTiles, EWARPS * 32>>>(h1, out);
}